// round 12
// baseline (speedup 1.0000x reference)
#include <cuda_runtime.h>

#define B_TOT   4096
#define T_STEPS 512
#define IN_W    4
#define H_DIM   64
#define TB      32
#define NTH     512
#define HS      36   // padded batch-row stride (floats); rows 16B-aligned

typedef unsigned long long ull;

// ---- sm_103a packed f32x2 helpers ----
__device__ __forceinline__ ull splat2(float x) {
    ull r; asm("mov.b64 %0, {%1, %1};" : "=l"(r) : "f"(x)); return r;
}
__device__ __forceinline__ ull pack2(float lo, float hi) {
    ull r; asm("mov.b64 %0, {%1, %2};" : "=l"(r) : "f"(lo), "f"(hi)); return r;
}
__device__ __forceinline__ ull fma2(ull a, ull b, ull c) {
    ull d; asm("fma.rn.f32x2 %0, %1, %2, %3;" : "=l"(d) : "l"(a), "l"(b), "l"(c)); return d;
}
__device__ __forceinline__ float2 unpack2(ull v) {
    float2 f; asm("mov.b64 {%0, %1}, %2;" : "=f"(f.x), "=f"(f.y) : "l"(v)); return f;
}

// ---- HW activations (MUFU.TANH) ----
__device__ __forceinline__ float tanhx(float x) {
    float y; asm("tanh.approx.f32 %0, %1;" : "=f"(y) : "f"(x)); return y;
}
__device__ __forceinline__ float sigx(float x) {
    return fmaf(tanhx(0.5f * x), 0.5f, 0.5f);
}

// SMEM layout (floats):
//  W1   [68][256]  @ 0      rows 0..63: Whh0 (transposed, gate-interleaved [k][j][g])
//                           rows 64..67: Wih0 (same interleave, k = input feature)
//  W2   [128][256] @ 17408  rows 0..63: Wih1, rows 64..127: Whh1
//  h1b  [64][HS]   @ 50176  h1 state [unit][batch]   (phase-A rows 0..63)
//  xb   [4][HS]    @ 52480  x_t [feature][batch]     (phase-A rows 64..67, contiguous!)
//  h2b  [64][HS]   @ 52624  h2 state
#define SM_W2   17408
#define SM_H1B  50176
#define SM_XB   52480
#define SM_H2B  52624
#define SM_TOT  54928   // floats = 219712 bytes

__global__ void __launch_bounds__(NTH, 1) lstm2_fused_kernel(
    const float* __restrict__ x,
    const float* __restrict__ Wih0, const float* __restrict__ Whh0,
    const float* __restrict__ bih0, const float* __restrict__ bhh0,
    const float* __restrict__ Wih1, const float* __restrict__ Whh1,
    const float* __restrict__ bih1, const float* __restrict__ bhh1,
    const float* __restrict__ Wfc,  const float* __restrict__ bfc,
    float* __restrict__ out)
{
    extern __shared__ float sm[];
    float* W1  = sm;
    float* W2  = sm + SM_W2;
    float* h1b = sm + SM_H1B;   // phase A reads rows 0..67 (xb is rows 64..67)
    float* xb  = sm + SM_XB;
    float* h2b = sm + SM_H2B;

    const int tid = threadIdx.x;
    const int j   = tid >> 3;        // gate unit 0..63
    const int q4  = (tid & 7) * 4;   // batch offset (4 batches per thread)
    const int b0  = blockIdx.x * TB;

    // ---- prologue: stage weights into SMEM, transposed + gate-interleaved ----
    for (int idx = tid; idx < 68 * 256; idx += NTH) {
        int k = idx >> 8, col = idx & 255;
        int r = ((col & 3) << 6) | (col >> 2);   // original gate row
        W1[idx] = (k < 64) ? Whh0[r * 64 + k] : Wih0[r * IN_W + (k - 64)];
    }
    for (int idx = tid; idx < 128 * 256; idx += NTH) {
        int k = idx >> 8, col = idx & 255;
        int r = ((col & 3) << 6) | (col >> 2);
        W2[idx] = (k < 64) ? Wih1[r * 64 + k] : Whh1[r * 64 + (k - 64)];
    }
    for (int idx = tid; idx < 64 * HS; idx += NTH) { h1b[idx] = 0.f; h2b[idx] = 0.f; }
    if (tid < TB) {
        const float4 x4 = *(const float4*)(x + ((size_t)(b0 + tid) * T_STEPS) * IN_W);
        xb[0 * HS + tid] = x4.x; xb[1 * HS + tid] = x4.y;
        xb[2 * HS + tid] = x4.z; xb[3 * HS + tid] = x4.w;
    }

    // fused biases, pre-splatted
    ull bs1[4], bs2[4];
    #pragma unroll
    for (int gg = 0; gg < 4; gg++) {
        int r = gg * 64 + j;
        bs1[gg] = splat2(bih0[r] + bhh0[r]);
        bs2[gg] = splat2(bih1[r] + bhh1[r]);
    }

    float c1[4], c2[4];
    #pragma unroll
    for (int i = 0; i < 4; i++) { c1[i] = 0.f; c2[i] = 0.f; }

    __syncthreads();

    const float4* W1v = (const float4*)W1;
    const float4* W2v = (const float4*)W2;

    for (int t = 0; t < T_STEPS; t++) {
        // ========= Phase A: layer-1 gates, K=68 ([h1_{t-1} ; x_t]) =========
        ull acc[4][2];
        #pragma unroll
        for (int gg = 0; gg < 4; gg++) { acc[gg][0] = bs1[gg]; acc[gg][1] = bs1[gg]; }

        #pragma unroll 4
        for (int k = 0; k < 68; k++) {
            float4 w4 = W1v[(k << 6) | j];
            ulonglong2 hv = *(const ulonglong2*)(h1b + k * HS + q4);
            ull w0 = splat2(w4.x), w1 = splat2(w4.y);
            ull w2 = splat2(w4.z), w3 = splat2(w4.w);
            acc[0][0] = fma2(hv.x, w0, acc[0][0]);
            acc[1][0] = fma2(hv.x, w1, acc[1][0]);
            acc[2][0] = fma2(hv.x, w2, acc[2][0]);
            acc[3][0] = fma2(hv.x, w3, acc[3][0]);
            acc[0][1] = fma2(hv.y, w0, acc[0][1]);
            acc[1][1] = fma2(hv.y, w1, acc[1][1]);
            acc[2][1] = fma2(hv.y, w2, acc[2][1]);
            acc[3][1] = fma2(hv.y, w3, acc[3][1]);
        }
        __syncthreads();   // sync1: all gates read h1b/xb before overwrite

        // ========= Phase B: layer-1 elementwise (4 cells/thread) =========
        float4 xnext;
        const bool ldx = (tid < TB) && (t + 1 < T_STEPS);
        if (ldx)
            xnext = *(const float4*)(x + ((size_t)(b0 + tid) * T_STEPS + (t + 1)) * IN_W);

        {
            ulonglong2 st;
            #pragma unroll
            for (int p = 0; p < 2; p++) {
                float2 gi = unpack2(acc[0][p]);
                float2 gf = unpack2(acc[1][p]);
                float2 gc = unpack2(acc[2][p]);
                float2 go = unpack2(acc[3][p]);
                float i0 = sigx(gi.x),  i1 = sigx(gi.y);
                float f0 = sigx(gf.x),  f1 = sigx(gf.y);
                float g0 = tanhx(gc.x), g1 = tanhx(gc.y);
                float o0 = sigx(go.x),  o1 = sigx(go.y);
                float cn0 = fmaf(f0, c1[2*p],     i0 * g0);
                float cn1 = fmaf(f1, c1[2*p + 1], i1 * g1);
                c1[2*p] = cn0; c1[2*p + 1] = cn1;
                ull hp = pack2(o0 * tanhx(cn0), o1 * tanhx(cn1));
                if (p == 0) st.x = hp; else st.y = hp;
            }
            *(ulonglong2*)(h1b + j * HS + q4) = st;
        }
        if (ldx) {
            xb[0 * HS + tid] = xnext.x; xb[1 * HS + tid] = xnext.y;
            xb[2 * HS + tid] = xnext.z; xb[3 * HS + tid] = xnext.w;
        }
        __syncthreads();   // sync2: h1b (layer-2 input) ready

        // ===== Phase C: layer-2 gates, K=128 ([h1_t ; h2_{t-1}]) =====
        #pragma unroll
        for (int gg = 0; gg < 4; gg++) { acc[gg][0] = bs2[gg]; acc[gg][1] = bs2[gg]; }

        #pragma unroll 4
        for (int k = 0; k < 64; k++) {
            float4 w4 = W2v[(k << 6) | j];
            ulonglong2 hv = *(const ulonglong2*)(h1b + k * HS + q4);
            ull w0 = splat2(w4.x), w1 = splat2(w4.y);
            ull w2 = splat2(w4.z), w3 = splat2(w4.w);
            acc[0][0] = fma2(hv.x, w0, acc[0][0]);
            acc[1][0] = fma2(hv.x, w1, acc[1][0]);
            acc[2][0] = fma2(hv.x, w2, acc[2][0]);
            acc[3][0] = fma2(hv.x, w3, acc[3][0]);
            acc[0][1] = fma2(hv.y, w0, acc[0][1]);
            acc[1][1] = fma2(hv.y, w1, acc[1][1]);
            acc[2][1] = fma2(hv.y, w2, acc[2][1]);
            acc[3][1] = fma2(hv.y, w3, acc[3][1]);
        }
        #pragma unroll 4
        for (int k = 0; k < 64; k++) {
            float4 w4 = W2v[((64 + k) << 6) | j];
            ulonglong2 hv = *(const ulonglong2*)(h2b + k * HS + q4);
            ull w0 = splat2(w4.x), w1 = splat2(w4.y);
            ull w2 = splat2(w4.z), w3 = splat2(w4.w);
            acc[0][0] = fma2(hv.x, w0, acc[0][0]);
            acc[1][0] = fma2(hv.x, w1, acc[1][0]);
            acc[2][0] = fma2(hv.x, w2, acc[2][0]);
            acc[3][0] = fma2(hv.x, w3, acc[3][0]);
            acc[0][1] = fma2(hv.y, w0, acc[0][1]);
            acc[1][1] = fma2(hv.y, w1, acc[1][1]);
            acc[2][1] = fma2(hv.y, w2, acc[2][1]);
            acc[3][1] = fma2(hv.y, w3, acc[3][1]);
        }
        __syncthreads();   // sync3: all reads of h2b done before D overwrites

        // ========= Phase D: layer-2 elementwise =========
        {
            ulonglong2 st;
            #pragma unroll
            for (int p = 0; p < 2; p++) {
                float2 gi = unpack2(acc[0][p]);
                float2 gf = unpack2(acc[1][p]);
                float2 gc = unpack2(acc[2][p]);
                float2 go = unpack2(acc[3][p]);
                float i0 = sigx(gi.x),  i1 = sigx(gi.y);
                float f0 = sigx(gf.x),  f1 = sigx(gf.y);
                float g0 = tanhx(gc.x), g1 = tanhx(gc.y);
                float o0 = sigx(go.x),  o1 = sigx(go.y);
                float cn0 = fmaf(f0, c2[2*p],     i0 * g0);
                float cn1 = fmaf(f1, c2[2*p + 1], i1 * g1);
                c2[2*p] = cn0; c2[2*p + 1] = cn1;
                ull hp = pack2(o0 * tanhx(cn0), o1 * tanhx(cn1));
                if (p == 0) st.x = hp; else st.y = hp;
            }
            *(ulonglong2*)(h2b + j * HS + q4) = st;
        }
        // no sync: next Phase A touches h1b/xb only; D->C' ordered by sync1'+sync2'
    }
    __syncthreads();

    // ================= FC head: out[b] = h2_final @ Wfc^T + bfc =================
    for (int tt = tid; tt < TB * 20; tt += NTH) {
        int bb = tt / 20, o = tt % 20;
        float s = bfc[o];
        #pragma unroll 8
        for (int jj = 0; jj < 64; jj++)
            s += h2b[jj * HS + bb] * Wfc[o * 64 + jj];
        out[(size_t)(b0 + bb) * 20 + o] = s;
    }
}

extern "C" void kernel_launch(void* const* d_in, const int* in_sizes, int n_in,
                              void* d_out, int out_size) {
    const float* x    = (const float*)d_in[0];
    const float* Wih0 = (const float*)d_in[1];
    const float* Whh0 = (const float*)d_in[2];
    const float* bih0 = (const float*)d_in[3];
    const float* bhh0 = (const float*)d_in[4];
    const float* Wih1 = (const float*)d_in[5];
    const float* Whh1 = (const float*)d_in[6];
    const float* bih1 = (const float*)d_in[7];
    const float* bhh1 = (const float*)d_in[8];
    const float* Wfc  = (const float*)d_in[9];
    const float* bfc  = (const float*)d_in[10];
    float* out = (float*)d_out;

    const size_t smem = (size_t)SM_TOT * sizeof(float);
    cudaFuncSetAttribute(lstm2_fused_kernel,
                         cudaFuncAttributeMaxDynamicSharedMemorySize, (int)smem);
    lstm2_fused_kernel<<<B_TOT / TB, NTH, smem>>>(
        x, Wih0, Whh0, bih0, bhh0, Wih1, Whh1, bih1, bhh1, Wfc, bfc, out);
}